// round 13
// baseline (speedup 1.0000x reference)
#include <cuda_runtime.h>
#include <math_constants.h>

// Sampler: B=256 rows, V=128000 vocab.
// inputs: logits [B,V] f32, temperatures [B] f32, uniform_noise [B,V] f32
// output: [tokens (B floats)] ++ [probs (B*V floats)]

#define NT 1024
#define BB 256
#define VV 128000
#define NV8 (VV / 8)                  // 16000 float8 chunks per row (pass 1)
#define NV4 (VV / 4)                  // 32000 float4 chunks per row (pass 2)
#define L2E 1.4426950408889634f

__device__ __forceinline__ float lg2a(float x) {
    float r; asm("lg2.approx.f32 %0, %1;" : "=f"(r) : "f"(x)); return r;
}
__device__ __forceinline__ float ex2a(float x) {
    float r; asm("ex2.approx.f32 %0, %1;" : "=f"(r) : "f"(x)); return r;
}
// 32-byte logits load, pinned toward L2 retention for the pass-2 reread.
// (sm_103a ptxas requires .v8.b32/.v4.b64 with L2::evict_last)
__device__ __forceinline__ void ldg_el8(const float* p, float v[8]) {
    unsigned long long a0, a1, a2, a3;
    asm("ld.global.L2::evict_last.v4.b64 {%0,%1,%2,%3}, [%4];"
        : "=l"(a0), "=l"(a1), "=l"(a2), "=l"(a3) : "l"(p));
    v[0] = __uint_as_float((unsigned)(a0));  v[1] = __uint_as_float((unsigned)(a0 >> 32));
    v[2] = __uint_as_float((unsigned)(a1));  v[3] = __uint_as_float((unsigned)(a1 >> 32));
    v[4] = __uint_as_float((unsigned)(a2));  v[5] = __uint_as_float((unsigned)(a2 >> 32));
    v[6] = __uint_as_float((unsigned)(a3));  v[7] = __uint_as_float((unsigned)(a3 >> 32));
}

__global__ void __launch_bounds__(NT, 2)   // cap regs at 32 -> 2 blocks/SM
sampler_kernel(const float* __restrict__ logits,
               const float* __restrict__ temps,
               const float* __restrict__ noise,
               float* __restrict__ out)
{
    const int b    = blockIdx.x;
    const int tid  = threadIdx.x;
    const int lane = tid & 31;
    const int wid  = tid >> 5;            // 0..31

    const float t      = temps[b];
    const float safe_t = (t == 0.0f) ? 1.0f : t;
    const float inv_t  = 1.0f / safe_t;
    const float a      = inv_t * L2E;     // logit -> log2-domain scale

    const float* __restrict__ lrow = logits + (size_t)b * VV;
    const float* __restrict__ nrow = noise  + (size_t)b * VV;
    float4* __restrict__ prow      = (float4*)(out + BB + (size_t)b * VV);

    // pass 1: greedy argmax (gv,gi) + online exp-sum s + Gumbel argmax in the
    // EXP domain: argmax(scaled+g) == argmax( exp(scaled) / (-log u) ).
    // e = exp2((l-gv)*a) serves BOTH the sum and the Gumbel candidate;
    // sv holds the best w = e/y2 in current-base units (rescales with s).
    float gv = -CUDART_INF_F; int gi = 0;
    float s  = 0.0f;
    float sv = 0.0f;          int si = 0;

    for (int j = tid; j < NV8; j += NT) {
        float lv[8];
        ldg_el8(lrow + 8 * j, lv);
        // consume in two 4-wide halves to keep live ranges small
        #pragma unroll
        for (int h = 0; h < 2; h++) {
            const float4 n4 = __ldcs((const float4*)(nrow + 8 * j) + h);
            const float nv[4] = {n4.x, n4.y, n4.z, n4.w};
            #pragma unroll
            for (int k = 0; k < 4; k++) {
                const int idx = 8 * j + 4 * h + k;
                const float l = lv[4 * h + k];
                const float u = nv[k];
                float e;
                if (l > gv) {                       // rare: new running max
                    const float f = ex2a((gv - l) * a);   // exp2(-inf)=0 first time
                    s  = s * f;
                    sv = sv * f;                    // keep w-units consistent
                    gv = l; gi = idx;
                    e = 1.0f;                       // exp2(0) for the new max
                } else {
                    e = ex2a((l - gv) * a);
                }
                s += e;
                // y2 = -log2(u); exact series (pre-scaled by log2e) for u -> 1
                float y2 = 0.0f - lg2a(u);
                const float d = 1.0f - u;
                if (u > 0.99f)
                    y2 = d * fmaf(d, fmaf(d, 0.48089835f, 0.72134752f), 1.44269504f);
                // Gumbel candidate: w = e/y2 > sv  <=>  e > sv*y2
                if (e > sv * y2) { sv = __fdividef(e, y2); si = idx; }
            }
        }
    }

    // convert per-thread Gumbel best to an absolute log2 key for reduction
    float skey = fmaf(gv, a, lg2a(sv));   // log2(w_abs); sv>0 always (NV8 >= NT)

    // ---- block reductions ----
    __shared__ float sh_gv[32]; __shared__ int sh_gi[32];
    __shared__ float sh_sv[32]; __shared__ int sh_si[32];
    __shared__ float sh_sum[32];
    __shared__ float fin_c;

    #pragma unroll
    for (int off = 16; off; off >>= 1) {
        float v  = __shfl_xor_sync(0xffffffffu, gv, off);
        int   i  = __shfl_xor_sync(0xffffffffu, gi, off);
        float ws = __shfl_xor_sync(0xffffffffu, s, off);
        if (v > gv) { s = fmaf(s, ex2a((gv - v) * a), ws); gv = v; gi = i; }
        else {
            s = fmaf(ws, ex2a((v - gv) * a), s);
            if (v == gv && i < gi) gi = i;
        }
        float v2 = __shfl_xor_sync(0xffffffffu, skey, off);
        int   i2 = __shfl_xor_sync(0xffffffffu, si, off);
        if (v2 > skey || (v2 == skey && i2 < si)) { skey = v2; si = i2; }
    }
    if (lane == 0) {
        sh_gv[wid] = gv; sh_gi[wid] = gi; sh_sum[wid] = s;
        sh_sv[wid] = skey; sh_si[wid] = si;
    }
    __syncthreads();

    if (wid == 0) {
        float v = sh_gv[lane]; int i = sh_gi[lane]; float c = sh_sum[lane];
        float v2 = sh_sv[lane]; int i2 = sh_si[lane];
        #pragma unroll
        for (int off = 16; off; off >>= 1) {
            float wv = __shfl_xor_sync(0xffffffffu, v, off);
            int   wi = __shfl_xor_sync(0xffffffffu, i, off);
            float wc = __shfl_xor_sync(0xffffffffu, c, off);
            if (wv > v) { c = fmaf(c, ex2a((v - wv) * a), wc); v = wv; i = wi; }
            else {
                c = fmaf(wc, ex2a((wv - v) * a), c);
                if (wv == v && wi < i) i = wi;
            }
            float wv2 = __shfl_xor_sync(0xffffffffu, v2, off);
            int   wi2 = __shfl_xor_sync(0xffffffffu, i2, off);
            if (wv2 > v2 || (wv2 == v2 && wi2 < i2)) { v2 = wv2; i2 = wi2; }
        }
        if (lane == 0) {
            // probs = exp2(l*a - max*a - log2(sum))
            fin_c = fmaf(-v, a, -log2f(c));
            out[b] = (float)((t == 0.0f) ? i : i2);
        }
    }
    __syncthreads();

    // ---- pass 2: probs = exp2(l*a + c) ----
    // REVERSE order (LIFO): the row tail is the freshest L2 content after
    // pass 1; consuming most-recent-first maximizes hits under LRU.
    // Unrolled x2 for per-thread MLP in the load->EX2->store chain.
    const float c = fin_c;
    const float4* __restrict__ lrow4 = (const float4*)lrow;
    int j = NV4 - NT + tid;               // top chunk for this thread
    for (; j >= NT; j -= 2 * NT) {
        const float4 la = lrow4[j];
        const float4 lb = lrow4[j - NT];
        float4 pa, pb;
        pa.x = ex2a(fmaf(la.x, a, c)); pa.y = ex2a(fmaf(la.y, a, c));
        pa.z = ex2a(fmaf(la.z, a, c)); pa.w = ex2a(fmaf(la.w, a, c));
        pb.x = ex2a(fmaf(lb.x, a, c)); pb.y = ex2a(fmaf(lb.y, a, c));
        pb.z = ex2a(fmaf(lb.z, a, c)); pb.w = ex2a(fmaf(lb.w, a, c));
        __stcs(prow + j, pa);
        __stcs(prow + (j - NT), pb);
    }
    if (j >= 0) {
        const float4 la = lrow4[j];
        float4 pa;
        pa.x = ex2a(fmaf(la.x, a, c)); pa.y = ex2a(fmaf(la.y, a, c));
        pa.z = ex2a(fmaf(la.z, a, c)); pa.w = ex2a(fmaf(la.w, a, c));
        __stcs(prow + j, pa);
    }
}

extern "C" void kernel_launch(void* const* d_in, const int* in_sizes, int n_in,
                              void* d_out, int out_size) {
    const float* logits = (const float*)d_in[0];
    const float* temps  = (const float*)d_in[1];
    const float* noise  = (const float*)d_in[2];
    float* out = (float*)d_out;
    sampler_kernel<<<BB, NT>>>(logits, temps, noise, out);
}